// round 10
// baseline (speedup 1.0000x reference)
#include <cuda_runtime.h>
#include <cuda_fp16.h>
#include <cstdint>
#include <math.h>

#define BATCH 16
#define SEQ   1024
#define EDIM  512
#define NROWS (BATCH*SEQ)
#define TOTALF ((float)((double)BATCH*SEQ*SEQ))
#define TEMP  13.544f
#define EPSV  1e-5f
#define DSCALE 16.0f
#define INV_DSCALE (1.0f/16.0f)

// ---------------- device scratch (no allocations allowed) ------------------
__device__ __half g_h[(size_t)NROWS * EDIM];                 // 16 MB fp16 x
__device__ unsigned short g_d[(size_t)BATCH * SEQ * SEQ];    // 32 MB u16 d*16
__device__ float  g_sq[NROWS];
__device__ double g_sum;
__device__ double g_sumsq;

// ---------------- PTX helpers ----------------------------------------------
__device__ __forceinline__ uint32_t smem_u32(const void* p) {
    uint32_t a;
    asm("{ .reg .u64 t; cvta.to.shared.u64 t, %1; cvt.u32.u64 %0, t; }" : "=r"(a) : "l"(p));
    return a;
}
__device__ __forceinline__ void cp16(uint32_t dst, const void* src) {
    asm volatile("cp.async.cg.shared.global [%0], [%1], 16;" :: "r"(dst), "l"(src));
}
#define CP_COMMIT() asm volatile("cp.async.commit_group;" ::: "memory")
#define CP_WAIT(n)  asm volatile("cp.async.wait_group %0;" :: "n"(n) : "memory")

__device__ __forceinline__ void ldm4(uint32_t* r, uint32_t addr) {
    asm volatile("ldmatrix.sync.aligned.m8n8.x4.shared.b16 {%0,%1,%2,%3}, [%4];"
                 : "=r"(r[0]), "=r"(r[1]), "=r"(r[2]), "=r"(r[3]) : "r"(addr));
}
__device__ __forceinline__ void mma16816(float* c, const uint32_t* a,
                                         uint32_t b0, uint32_t b1) {
    asm volatile("mma.sync.aligned.m16n8k16.row.col.f32.f16.f16.f32 "
                 "{%0,%1,%2,%3}, {%4,%5,%6,%7}, {%8,%9}, {%0,%1,%2,%3};"
                 : "+f"(c[0]), "+f"(c[1]), "+f"(c[2]), "+f"(c[3])
                 : "r"(a[0]), "r"(a[1]), "r"(a[2]), "r"(a[3]), "r"(b0), "r"(b1));
}
__device__ __forceinline__ unsigned short q16(float d) {
    unsigned u = __float2uint_rn(d * DSCALE);
    return (unsigned short)(u > 65535u ? 65535u : u);
}

// ---------------- gram geometry (round-6 winner mainloop) ------------------
#define KC        32
#define NCHUNK    (EDIM / KC)              // 16
#define TROWB     80
#define TILE_B    (128 * TROWB)            // 10240
#define NTILES    2                        // A, B
#define BUF_B     (NTILES * TILE_B)        // 20480
#define SM_SQA    0
#define SM_SQB    512
#define SM_RED    1024
#define SM_REDQ   1056
#define SM_TILES  2048
#define TRPAD     129                      // staging 128*129*4 = 66048
#define GRAM_SMEM (SM_TILES + 128 * TRPAD * 4)   // 68096

// ---------------------------------------------------------------------------
// Kernel 1: fp32 -> fp16 + per-row squared norms (8 floats -> one 16B store).
// ---------------------------------------------------------------------------
__global__ __launch_bounds__(256)
void conv_kernel(const float* __restrict__ x) {
    if (blockIdx.x == 0 && threadIdx.x == 0) { g_sum = 0.0; g_sumsq = 0.0; }
    int gw   = (blockIdx.x * blockDim.x + threadIdx.x) >> 5;
    int lane = threadIdx.x & 31;
    if (gw >= NROWS) return;
    const float4* row = (const float4*)(x + (size_t)gw * EDIM);
    uint4* op = (uint4*)(g_h + (size_t)gw * EDIM);
    float s = 0.f;
    #pragma unroll
    for (int p = 0; p < 2; p++) {
        int u = lane + 32 * p;
        float4 a = row[2 * u];
        float4 b = row[2 * u + 1];
        s += a.x*a.x + a.y*a.y + a.z*a.z + a.w*a.w;
        s += b.x*b.x + b.y*b.y + b.z*b.z + b.w*b.w;
        __half2 h[4];
        h[0] = __floats2half2_rn(a.x, a.y);
        h[1] = __floats2half2_rn(a.z, a.w);
        h[2] = __floats2half2_rn(b.x, b.y);
        h[3] = __floats2half2_rn(b.z, b.w);
        op[u] = *(uint4*)h;
    }
    #pragma unroll
    for (int o = 16; o > 0; o >>= 1) s += __shfl_xor_sync(0xffffffffu, s, o);
    if (lane == 0) g_sq[gw] = s;
}

// ---------------------------------------------------------------------------
// Kernel 2: symmetric fp16 Gram -> u16 fixed-point d (d*16).
// Mainloop = round-6 winner, unchanged. Epilogue: stage fp32 d in smem,
// then coalesced u16 row writes for both (ti,tj) and (tj,ti).
// ---------------------------------------------------------------------------
__device__ __forceinline__ void prefetch_chunk(
    const __half* A, const __half* B, uint32_t sb, int buf, int kc, int tid)
{
    const __half* panels[NTILES] = { A, B };
    int p = tid >> 6, s = tid & 63;
    const char* src = (const char*)panels[p] + kc * (KC * 2);
    uint32_t tb = sb + SM_TILES + buf * BUF_B + p * TILE_B;
    #pragma unroll
    for (int i = 0; i < 8; i++) {
        int idx = i * 64 + s;
        int row = idx >> 2;
        int q   = idx & 3;
        cp16(tb + row * TROWB + q * 16,
             src + (size_t)row * (EDIM * 2) + q * 16);
    }
}

__global__ __launch_bounds__(128, 2)
void gram_tc_kernel() {
    extern __shared__ char smem[];
    const uint32_t sb = smem_u32(smem);
    const int tid  = threadIdx.x;
    const int wid  = tid >> 5;
    const int lane = tid & 31;

    // decode upper-triangle tile pair (8x8 tiles, 36 pairs)
    int p = blockIdx.x, ti = 0;
    while (p >= 8 - ti) { p -= 8 - ti; ti++; }
    const int tj   = ti + p;
    const int b    = blockIdx.z;
    const int row0 = ti * 128;
    const int col0 = tj * 128;
    const int warp_m = (wid >> 1) * 64;
    const int warp_n = (wid & 1) * 64;

    const __half* A = g_h + ((size_t)(b * SEQ + row0)) * EDIM;
    const __half* B = g_h + ((size_t)(b * SEQ + col0)) * EDIM;

    if (tid < 128) {
        ((float*)(smem + SM_SQA))[tid] = g_sq[b * SEQ + row0 + tid];
        ((float*)(smem + SM_SQB))[tid] = g_sq[b * SEQ + col0 + tid];
    }

    float acc[4][8][4];
    #pragma unroll
    for (int mi = 0; mi < 4; mi++)
        #pragma unroll
        for (int ni = 0; ni < 8; ni++)
            #pragma unroll
            for (int k = 0; k < 4; k++) acc[mi][ni][k] = 0.f;

    const uint32_t aOff = (uint32_t)((warp_m + (lane & 15)) * TROWB + (lane >> 4) * 16);
    const uint32_t bOff = (uint32_t)((warp_n + (lane & 7) + ((lane >> 4) << 3)) * TROWB
                                     + ((lane >> 3) & 1) * 16);

    prefetch_chunk(A, B, sb, 0, 0, tid);
    CP_COMMIT();

    #pragma unroll 1
    for (int c = 0; c < NCHUNK; c++) {
        if (c + 1 < NCHUNK) {
            prefetch_chunk(A, B, sb, (c + 1) & 1, c + 1, tid);
            CP_COMMIT();
            CP_WAIT(1);
        } else {
            CP_WAIT(0);
        }
        __syncthreads();

        uint32_t base = sb + SM_TILES + (c & 1) * BUF_B;
        #pragma unroll
        for (int ks = 0; ks < 2; ks++) {
            const uint32_t kb = ks * 32;
            uint32_t aF[16], bb[16];
            #pragma unroll
            for (int mi = 0; mi < 4; mi++)
                ldm4(&aF[mi * 4], base + 0 * TILE_B + aOff + mi * 16 * TROWB + kb);
            #pragma unroll
            for (int nj = 0; nj < 4; nj++)
                ldm4(&bb[nj * 4], base + 1 * TILE_B + bOff + nj * 16 * TROWB + kb);
            #pragma unroll
            for (int mi = 0; mi < 4; mi++)
                #pragma unroll
                for (int ni = 0; ni < 8; ni++)
                    mma16816(acc[mi][ni], &aF[mi * 4], bb[ni * 2], bb[ni * 2 + 1]);
        }
        __syncthreads();
    }

    // ---------------- epilogue: stage fp32 d in smem, stats, u16 writes ---
    const int g  = lane >> 2;
    const int t4 = lane & 3;
    const float* sqA = (const float*)(smem + SM_SQA);
    const float* sqB = (const float*)(smem + SM_SQB);
    float* trb = (float*)(smem + SM_TILES);
    unsigned short* Dd = g_d + (size_t)b * SEQ * SEQ;
    const bool diag = (ti == tj);
    float fsum = 0.f, fsq = 0.f;
    #pragma unroll
    for (int mi = 0; mi < 4; mi++) {
        #pragma unroll
        for (int h = 0; h < 2; h++) {
            int rl = warp_m + mi * 16 + g + h * 8;
            float sr = sqA[rl];
            #pragma unroll
            for (int ni = 0; ni < 8; ni++) {
                int cl = warp_n + ni * 8 + t4 * 2;
                float d0 = fmaxf(sr + sqB[cl]     - 2.f * acc[mi][ni][2 * h],     0.f);
                float d1 = fmaxf(sr + sqB[cl + 1] - 2.f * acc[mi][ni][2 * h + 1], 0.f);
                if (diag) {                    // exact-zero self distance
                    if (rl == cl)     d0 = 0.f;
                    if (rl == cl + 1) d1 = 0.f;
                }
                fsum += d0 + d1;
                fsq  += d0 * d0 + d1 * d1;
                trb[rl * TRPAD + cl]     = d0;
                trb[rl * TRPAD + cl + 1] = d1;
            }
        }
    }
    __syncthreads();   // trb fully written

    // direct tile (ti,tj): thread r writes one contiguous u16 row of 128
    {
        int r = tid;
        unsigned short* op = Dd + (size_t)(row0 + r) * SEQ + col0;
        #pragma unroll
        for (int i = 0; i < 128; i += 4) {
            const float* tp = trb + r * TRPAD + i;
            ushort4 u;
            u.x = q16(tp[0]); u.y = q16(tp[1]);
            u.z = q16(tp[2]); u.w = q16(tp[3]);
            *(ushort4*)(op + i) = u;
        }
    }

    if (!diag) {       // transposed tile (tj,ti)
        int cc = tid;
        unsigned short* op = Dd + (size_t)(col0 + cc) * SEQ + row0;
        #pragma unroll
        for (int i = 0; i < 128; i += 4) {
            ushort4 u;
            u.x = q16(trb[(i + 0) * TRPAD + cc]);
            u.y = q16(trb[(i + 1) * TRPAD + cc]);
            u.z = q16(trb[(i + 2) * TRPAD + cc]);
            u.w = q16(trb[(i + 3) * TRPAD + cc]);
            *(ushort4*)(op + i) = u;
        }
        fsum *= 2.f; fsq *= 2.f;
    }

    // stats reduction (fp32 warp -> double CTA -> 2 atomics)
    #pragma unroll
    for (int o = 16; o > 0; o >>= 1) {
        fsum += __shfl_xor_sync(0xffffffffu, fsum, o);
        fsq  += __shfl_xor_sync(0xffffffffu, fsq,  o);
    }
    if (lane == 0) {
        ((double*)(smem + SM_RED))[wid]  = (double)fsum;
        ((double*)(smem + SM_REDQ))[wid] = (double)fsq;
    }
    __syncthreads();
    if (tid == 0) {
        double s = 0.0, q = 0.0;
        #pragma unroll
        for (int k = 0; k < 4; k++) {
            s += ((double*)(smem + SM_RED))[k];
            q += ((double*)(smem + SM_REDQ))[k];
        }
        atomicAdd(&g_sum, s);
        atomicAdd(&g_sumsq, q);
    }
}

// ---------------------------------------------------------------------------
// Kernel 3: warp-per-row softmax. Reads u16 d, writes fp32 probs to out.
// coef from global stats in FLOAT; dequant scale folded into coef.
// Row max analytically 0 when coef <= 0 (u_ii = 0 in every row).
// ---------------------------------------------------------------------------
__global__ __launch_bounds__(256)
void softmax_kernel(float* __restrict__ dout, const float* __restrict__ gamma) {
    const int wid  = threadIdx.x >> 5;
    const int lane = threadIdx.x & 31;
    const size_t row = (size_t)blockIdx.x * 8 + wid;
    const ushort4* ip = (const ushort4*)(g_d + row * SEQ);
    float4* op = (float4*)(dout + row * SEQ);

    const float fsum0 = (float)g_sum;
    const float fssq  = (float)g_sumsq;
    const float mean  = fsum0 * (1.f / TOTALF);
    const float var   = fssq * (1.f / TOTALF) - mean * mean;
    const float coef  = -gamma[0] * rsqrtf(var + EPSV) * (1.f / TEMP);
    const float c2    = coef * INV_DSCALE;

    // 32 values per thread: 8 ushort4 loads
    float t[32];
    #pragma unroll
    for (int i = 0; i < 8; i++) {
        ushort4 u = ip[lane + 32 * i];
        t[4*i+0] = c2 * (float)u.x;
        t[4*i+1] = c2 * (float)u.y;
        t[4*i+2] = c2 * (float)u.z;
        t[4*i+3] = c2 * (float)u.w;
    }

    float m = 0.f;
    if (coef > 0.f) {            // not taken for gamma>0; correctness guard
        m = -1e30f;
        #pragma unroll
        for (int j = 0; j < 32; j++) m = fmaxf(m, t[j]);
        #pragma unroll
        for (int o = 16; o > 0; o >>= 1) m = fmaxf(m, __shfl_xor_sync(0xffffffffu, m, o));
    }

    float s = 0.f;
    #pragma unroll
    for (int j = 0; j < 32; j++) { t[j] = __expf(t[j] - m); s += t[j]; }
    #pragma unroll
    for (int o = 16; o > 0; o >>= 1) s += __shfl_xor_sync(0xffffffffu, s, o);
    const float inv = 1.f / s;

    #pragma unroll
    for (int i = 0; i < 8; i++) {
        float4 v;
        v.x = t[4*i+0] * inv; v.y = t[4*i+1] * inv;
        v.z = t[4*i+2] * inv; v.w = t[4*i+3] * inv;
        op[lane + 32 * i] = v;
    }
}

// ---------------------------------------------------------------------------
extern "C" void kernel_launch(void* const* d_in, const int* in_sizes, int n_in,
                              void* d_out, int out_size) {
    const float* x     = (const float*)d_in[0];
    const float* gamma = (const float*)d_in[1];
    float* out = (float*)d_out;

    cudaFuncSetAttribute(gram_tc_kernel,
                         cudaFuncAttributeMaxDynamicSharedMemorySize, GRAM_SMEM);

    conv_kernel<<<NROWS * 32 / 256, 256>>>(x);
    dim3 grid(36, 1, BATCH);
    gram_tc_kernel<<<grid, 128, GRAM_SMEM>>>();
    softmax_kernel<<<NROWS / 8, 256>>>(out, gamma);
}

// round 11
// speedup vs baseline: 1.2278x; 1.2278x over previous
#include <cuda_runtime.h>
#include <cuda_fp16.h>
#include <cstdint>
#include <math.h>

#define BATCH 16
#define SEQ   1024
#define EDIM  512
#define NROWS (BATCH*SEQ)
#define TOTALF ((float)((double)BATCH*SEQ*SEQ))
#define TEMP  13.544f
#define EPSV  1e-5f
#define DSCALE 16.0f
#define INV_DSCALE (1.0f/16.0f)

// ---------------- device scratch (no allocations allowed) ------------------
__device__ __half g_h[(size_t)NROWS * EDIM];                 // 16 MB fp16 x
__device__ unsigned short g_d[(size_t)BATCH * SEQ * SEQ];    // 32 MB u16 d*16
__device__ float  g_sq[NROWS];
__device__ double g_sum;
__device__ double g_sumsq;

// ---------------- PTX helpers ----------------------------------------------
__device__ __forceinline__ uint32_t smem_u32(const void* p) {
    uint32_t a;
    asm("{ .reg .u64 t; cvta.to.shared.u64 t, %1; cvt.u32.u64 %0, t; }" : "=r"(a) : "l"(p));
    return a;
}
__device__ __forceinline__ void cp16(uint32_t dst, const void* src) {
    asm volatile("cp.async.cg.shared.global [%0], [%1], 16;" :: "r"(dst), "l"(src));
}
#define CP_COMMIT() asm volatile("cp.async.commit_group;" ::: "memory")
#define CP_WAIT(n)  asm volatile("cp.async.wait_group %0;" :: "n"(n) : "memory")

__device__ __forceinline__ void ldm4(uint32_t* r, uint32_t addr) {
    asm volatile("ldmatrix.sync.aligned.m8n8.x4.shared.b16 {%0,%1,%2,%3}, [%4];"
                 : "=r"(r[0]), "=r"(r[1]), "=r"(r[2]), "=r"(r[3]) : "r"(addr));
}
__device__ __forceinline__ void mma16816(float* c, const uint32_t* a,
                                         uint32_t b0, uint32_t b1) {
    asm volatile("mma.sync.aligned.m16n8k16.row.col.f32.f16.f16.f32 "
                 "{%0,%1,%2,%3}, {%4,%5,%6,%7}, {%8,%9}, {%0,%1,%2,%3};"
                 : "+f"(c[0]), "+f"(c[1]), "+f"(c[2]), "+f"(c[3])
                 : "r"(a[0]), "r"(a[1]), "r"(a[2]), "r"(a[3]), "r"(b0), "r"(b1));
}
__device__ __forceinline__ unsigned short q16(float d) {
    unsigned u = __float2uint_rn(d * DSCALE);
    return (unsigned short)(u > 65535u ? 65535u : u);
}

// ---------------- gram geometry (round-6 winner mainloop) ------------------
#define KC        32
#define NCHUNK    (EDIM / KC)              // 16
#define TROWB     80
#define TILE_B    (128 * TROWB)            // 10240
#define NTILES    2                        // A, B
#define BUF_B     (NTILES * TILE_B)        // 20480
#define SM_SQA    0
#define SM_SQB    512
#define SM_RED    1024
#define SM_REDQ   1056
#define SM_TILES  2048
#define TRPAD     129                      // staging 128*129*4 = 66048
#define GRAM_SMEM (SM_TILES + 128 * TRPAD * 4)   // 68096

// ---------------------------------------------------------------------------
// Kernel 1: fp32 -> fp16 + per-row squared norms (8 floats -> one 16B store).
// ---------------------------------------------------------------------------
__global__ __launch_bounds__(256)
void conv_kernel(const float* __restrict__ x) {
    if (blockIdx.x == 0 && threadIdx.x == 0) { g_sum = 0.0; g_sumsq = 0.0; }
    int gw   = (blockIdx.x * blockDim.x + threadIdx.x) >> 5;
    int lane = threadIdx.x & 31;
    if (gw >= NROWS) return;
    const float4* row = (const float4*)(x + (size_t)gw * EDIM);
    uint4* op = (uint4*)(g_h + (size_t)gw * EDIM);
    float s = 0.f;
    #pragma unroll
    for (int p = 0; p < 2; p++) {
        int u = lane + 32 * p;
        float4 a = row[2 * u];
        float4 b = row[2 * u + 1];
        s += a.x*a.x + a.y*a.y + a.z*a.z + a.w*a.w;
        s += b.x*b.x + b.y*b.y + b.z*b.z + b.w*b.w;
        __half2 h[4];
        h[0] = __floats2half2_rn(a.x, a.y);
        h[1] = __floats2half2_rn(a.z, a.w);
        h[2] = __floats2half2_rn(b.x, b.y);
        h[3] = __floats2half2_rn(b.z, b.w);
        op[u] = *(uint4*)h;
    }
    #pragma unroll
    for (int o = 16; o > 0; o >>= 1) s += __shfl_xor_sync(0xffffffffu, s, o);
    if (lane == 0) g_sq[gw] = s;
}

// ---------------------------------------------------------------------------
// Kernel 2: symmetric fp16 Gram -> u16 fixed-point d (d*16).
// Mainloop = round-6 winner, unchanged. Epilogue: stage fp32 d in smem,
// then WARP-COOPERATIVE coalesced u16 row writes (one 256B row per warp
// instruction) for both (ti,tj) and (tj,ti).
// ---------------------------------------------------------------------------
__device__ __forceinline__ void prefetch_chunk(
    const __half* A, const __half* B, uint32_t sb, int buf, int kc, int tid)
{
    const __half* panels[NTILES] = { A, B };
    int p = tid >> 6, s = tid & 63;
    const char* src = (const char*)panels[p] + kc * (KC * 2);
    uint32_t tb = sb + SM_TILES + buf * BUF_B + p * TILE_B;
    #pragma unroll
    for (int i = 0; i < 8; i++) {
        int idx = i * 64 + s;
        int row = idx >> 2;
        int q   = idx & 3;
        cp16(tb + row * TROWB + q * 16,
             src + (size_t)row * (EDIM * 2) + q * 16);
    }
}

__global__ __launch_bounds__(128, 2)
void gram_tc_kernel() {
    extern __shared__ char smem[];
    const uint32_t sb = smem_u32(smem);
    const int tid  = threadIdx.x;
    const int wid  = tid >> 5;
    const int lane = tid & 31;

    // decode upper-triangle tile pair (8x8 tiles, 36 pairs)
    int p = blockIdx.x, ti = 0;
    while (p >= 8 - ti) { p -= 8 - ti; ti++; }
    const int tj   = ti + p;
    const int b    = blockIdx.z;
    const int row0 = ti * 128;
    const int col0 = tj * 128;
    const int warp_m = (wid >> 1) * 64;
    const int warp_n = (wid & 1) * 64;

    const __half* A = g_h + ((size_t)(b * SEQ + row0)) * EDIM;
    const __half* B = g_h + ((size_t)(b * SEQ + col0)) * EDIM;

    if (tid < 128) {
        ((float*)(smem + SM_SQA))[tid] = g_sq[b * SEQ + row0 + tid];
        ((float*)(smem + SM_SQB))[tid] = g_sq[b * SEQ + col0 + tid];
    }

    float acc[4][8][4];
    #pragma unroll
    for (int mi = 0; mi < 4; mi++)
        #pragma unroll
        for (int ni = 0; ni < 8; ni++)
            #pragma unroll
            for (int k = 0; k < 4; k++) acc[mi][ni][k] = 0.f;

    const uint32_t aOff = (uint32_t)((warp_m + (lane & 15)) * TROWB + (lane >> 4) * 16);
    const uint32_t bOff = (uint32_t)((warp_n + (lane & 7) + ((lane >> 4) << 3)) * TROWB
                                     + ((lane >> 3) & 1) * 16);

    prefetch_chunk(A, B, sb, 0, 0, tid);
    CP_COMMIT();

    #pragma unroll 1
    for (int c = 0; c < NCHUNK; c++) {
        if (c + 1 < NCHUNK) {
            prefetch_chunk(A, B, sb, (c + 1) & 1, c + 1, tid);
            CP_COMMIT();
            CP_WAIT(1);
        } else {
            CP_WAIT(0);
        }
        __syncthreads();

        uint32_t base = sb + SM_TILES + (c & 1) * BUF_B;
        #pragma unroll
        for (int ks = 0; ks < 2; ks++) {
            const uint32_t kb = ks * 32;
            uint32_t aF[16], bb[16];
            #pragma unroll
            for (int mi = 0; mi < 4; mi++)
                ldm4(&aF[mi * 4], base + 0 * TILE_B + aOff + mi * 16 * TROWB + kb);
            #pragma unroll
            for (int nj = 0; nj < 4; nj++)
                ldm4(&bb[nj * 4], base + 1 * TILE_B + bOff + nj * 16 * TROWB + kb);
            #pragma unroll
            for (int mi = 0; mi < 4; mi++)
                #pragma unroll
                for (int ni = 0; ni < 8; ni++)
                    mma16816(acc[mi][ni], &aF[mi * 4], bb[ni * 2], bb[ni * 2 + 1]);
        }
        __syncthreads();
    }

    // ---------------- epilogue: stage fp32 d in smem, stats, u16 writes ---
    const int g  = lane >> 2;
    const int t4 = lane & 3;
    const float* sqA = (const float*)(smem + SM_SQA);
    const float* sqB = (const float*)(smem + SM_SQB);
    float* trb = (float*)(smem + SM_TILES);
    unsigned short* Dd = g_d + (size_t)b * SEQ * SEQ;
    const bool diag = (ti == tj);
    float fsum = 0.f, fsq = 0.f;
    #pragma unroll
    for (int mi = 0; mi < 4; mi++) {
        #pragma unroll
        for (int h = 0; h < 2; h++) {
            int rl = warp_m + mi * 16 + g + h * 8;
            float sr = sqA[rl];
            #pragma unroll
            for (int ni = 0; ni < 8; ni++) {
                int cl = warp_n + ni * 8 + t4 * 2;
                float d0 = fmaxf(sr + sqB[cl]     - 2.f * acc[mi][ni][2 * h],     0.f);
                float d1 = fmaxf(sr + sqB[cl + 1] - 2.f * acc[mi][ni][2 * h + 1], 0.f);
                if (diag) {                    // exact-zero self distance
                    if (rl == cl)     d0 = 0.f;
                    if (rl == cl + 1) d1 = 0.f;
                }
                fsum += d0 + d1;
                fsq  += d0 * d0 + d1 * d1;
                trb[rl * TRPAD + cl]     = d0;
                trb[rl * TRPAD + cl + 1] = d1;
            }
        }
    }
    __syncthreads();   // trb fully written

    // direct tile (ti,tj): warp handles 32 rows; per row, 32 lanes x ushort4
    // = 256B fully-coalesced store.
    #pragma unroll 4
    for (int r32 = 0; r32 < 32; r32++) {
        int r = wid * 32 + r32;
        const float* tp = trb + r * TRPAD + lane * 4;
        ushort4 u;
        u.x = q16(tp[0]); u.y = q16(tp[1]);
        u.z = q16(tp[2]); u.w = q16(tp[3]);
        *(ushort4*)(Dd + (size_t)(row0 + r) * SEQ + col0 + lane * 4) = u;
    }

    if (!diag) {       // transposed tile (tj,ti): same coalesced row pattern,
                       // gathering a smem column (TRPAD=129 -> conflict-free)
        #pragma unroll 4
        for (int r32 = 0; r32 < 32; r32++) {
            int cc = wid * 32 + r32;
            ushort4 u;
            u.x = q16(trb[(lane * 4 + 0) * TRPAD + cc]);
            u.y = q16(trb[(lane * 4 + 1) * TRPAD + cc]);
            u.z = q16(trb[(lane * 4 + 2) * TRPAD + cc]);
            u.w = q16(trb[(lane * 4 + 3) * TRPAD + cc]);
            *(ushort4*)(Dd + (size_t)(col0 + cc) * SEQ + row0 + lane * 4) = u;
        }
        fsum *= 2.f; fsq *= 2.f;
    }

    // stats reduction (fp32 warp -> double CTA -> 2 atomics)
    #pragma unroll
    for (int o = 16; o > 0; o >>= 1) {
        fsum += __shfl_xor_sync(0xffffffffu, fsum, o);
        fsq  += __shfl_xor_sync(0xffffffffu, fsq,  o);
    }
    if (lane == 0) {
        ((double*)(smem + SM_RED))[wid]  = (double)fsum;
        ((double*)(smem + SM_REDQ))[wid] = (double)fsq;
    }
    __syncthreads();
    if (tid == 0) {
        double s = 0.0, q = 0.0;
        #pragma unroll
        for (int k = 0; k < 4; k++) {
            s += ((double*)(smem + SM_RED))[k];
            q += ((double*)(smem + SM_REDQ))[k];
        }
        atomicAdd(&g_sum, s);
        atomicAdd(&g_sumsq, q);
    }
}

// ---------------------------------------------------------------------------
// Kernel 3: warp-per-row softmax. Reads u16 d, writes fp32 probs to out.
// coef from global stats in FLOAT; dequant scale folded into coef.
// Row max analytically 0 when coef <= 0 (u_ii = 0 in every row).
// ---------------------------------------------------------------------------
__global__ __launch_bounds__(256)
void softmax_kernel(float* __restrict__ dout, const float* __restrict__ gamma) {
    const int wid  = threadIdx.x >> 5;
    const int lane = threadIdx.x & 31;
    const size_t row = (size_t)blockIdx.x * 8 + wid;
    const ushort4* ip = (const ushort4*)(g_d + row * SEQ);
    float4* op = (float4*)(dout + row * SEQ);

    const float fsum0 = (float)g_sum;
    const float fssq  = (float)g_sumsq;
    const float mean  = fsum0 * (1.f / TOTALF);
    const float var   = fssq * (1.f / TOTALF) - mean * mean;
    const float coef  = -gamma[0] * rsqrtf(var + EPSV) * (1.f / TEMP);
    const float c2    = coef * INV_DSCALE;

    float t[32];
    #pragma unroll
    for (int i = 0; i < 8; i++) {
        ushort4 u = ip[lane + 32 * i];
        t[4*i+0] = c2 * (float)u.x;
        t[4*i+1] = c2 * (float)u.y;
        t[4*i+2] = c2 * (float)u.z;
        t[4*i+3] = c2 * (float)u.w;
    }

    float m = 0.f;
    if (coef > 0.f) {            // not taken for gamma>0; correctness guard
        m = -1e30f;
        #pragma unroll
        for (int j = 0; j < 32; j++) m = fmaxf(m, t[j]);
        #pragma unroll
        for (int o = 16; o > 0; o >>= 1) m = fmaxf(m, __shfl_xor_sync(0xffffffffu, m, o));
    }

    float s = 0.f;
    #pragma unroll
    for (int j = 0; j < 32; j++) { t[j] = __expf(t[j] - m); s += t[j]; }
    #pragma unroll
    for (int o = 16; o > 0; o >>= 1) s += __shfl_xor_sync(0xffffffffu, s, o);
    const float inv = 1.f / s;

    #pragma unroll
    for (int i = 0; i < 8; i++) {
        float4 v;
        v.x = t[4*i+0] * inv; v.y = t[4*i+1] * inv;
        v.z = t[4*i+2] * inv; v.w = t[4*i+3] * inv;
        op[lane + 32 * i] = v;
    }
}

// ---------------------------------------------------------------------------
extern "C" void kernel_launch(void* const* d_in, const int* in_sizes, int n_in,
                              void* d_out, int out_size) {
    const float* x     = (const float*)d_in[0];
    const float* gamma = (const float*)d_in[1];
    float* out = (float*)d_out;

    cudaFuncSetAttribute(gram_tc_kernel,
                         cudaFuncAttributeMaxDynamicSharedMemorySize, GRAM_SMEM);

    conv_kernel<<<NROWS * 32 / 256, 256>>>(x);
    dim3 grid(36, 1, BATCH);
    gram_tc_kernel<<<grid, 128, GRAM_SMEM>>>();
    softmax_kernel<<<NROWS / 8, 256>>>(out, gamma);
}

// round 12
// speedup vs baseline: 1.2492x; 1.0174x over previous
#include <cuda_runtime.h>
#include <cuda_fp16.h>
#include <cstdint>
#include <math.h>

#define BATCH 16
#define SEQ   1024
#define EDIM  512
#define NROWS (BATCH*SEQ)
#define TOTALF ((float)((double)BATCH*SEQ*SEQ))
#define TEMP  13.544f
#define EPSV  1e-5f
#define DSCALE 16.0f
#define INV_DSCALE (1.0f/16.0f)

// ---------------- device scratch (no allocations allowed) ------------------
__device__ __half g_h[(size_t)NROWS * EDIM];                 // 16 MB fp16 x
__device__ unsigned short g_d[(size_t)BATCH * SEQ * SEQ];    // 32 MB u16 d*16
__device__ float  g_sq[NROWS];
__device__ double g_sum;
__device__ double g_sumsq;

// ---------------- PTX helpers ----------------------------------------------
__device__ __forceinline__ uint32_t smem_u32(const void* p) {
    uint32_t a;
    asm("{ .reg .u64 t; cvta.to.shared.u64 t, %1; cvt.u32.u64 %0, t; }" : "=r"(a) : "l"(p));
    return a;
}
__device__ __forceinline__ void cp16(uint32_t dst, const void* src) {
    asm volatile("cp.async.cg.shared.global [%0], [%1], 16;" :: "r"(dst), "l"(src));
}
#define CP_COMMIT() asm volatile("cp.async.commit_group;" ::: "memory")
#define CP_WAIT(n)  asm volatile("cp.async.wait_group %0;" :: "n"(n) : "memory")

__device__ __forceinline__ void ldm4(uint32_t* r, uint32_t addr) {
    asm volatile("ldmatrix.sync.aligned.m8n8.x4.shared.b16 {%0,%1,%2,%3}, [%4];"
                 : "=r"(r[0]), "=r"(r[1]), "=r"(r[2]), "=r"(r[3]) : "r"(addr));
}
__device__ __forceinline__ void mma16816(float* c, const uint32_t* a,
                                         uint32_t b0, uint32_t b1) {
    asm volatile("mma.sync.aligned.m16n8k16.row.col.f32.f16.f16.f32 "
                 "{%0,%1,%2,%3}, {%4,%5,%6,%7}, {%8,%9}, {%0,%1,%2,%3};"
                 : "+f"(c[0]), "+f"(c[1]), "+f"(c[2]), "+f"(c[3])
                 : "r"(a[0]), "r"(a[1]), "r"(a[2]), "r"(a[3]), "r"(b0), "r"(b1));
}
__device__ __forceinline__ unsigned short q16(float d) {
    unsigned u = __float2uint_rn(d * DSCALE);
    return (unsigned short)(u > 65535u ? 65535u : u);
}

// ---------------- gram geometry: KC=64 (8 chunks, 16 barriers) -------------
#define KC        64
#define NCHUNK    (EDIM / KC)              // 8
#define TROWB     144                      // 128B data + 16B pad (stride%128=16)
#define TILE_B    (128 * TROWB)            // 18432
#define NTILES    2                        // A, B
#define BUF_B     (NTILES * TILE_B)        // 36864
#define SM_SQA    0
#define SM_SQB    512
#define SM_RED    1024
#define SM_REDQ   1056
#define SM_TILES  2048
#define TRPAD     129                      // fp32 staging 128*129*4=66048 <= 2*BUF_B
#define GRAM_SMEM (SM_TILES + 2 * BUF_B)   // 75776 -> 2 CTAs/SM

// ---------------------------------------------------------------------------
// Kernel 1: fp32 -> fp16 + per-row squared norms (8 floats -> one 16B store).
// ---------------------------------------------------------------------------
__global__ __launch_bounds__(256)
void conv_kernel(const float* __restrict__ x) {
    if (blockIdx.x == 0 && threadIdx.x == 0) { g_sum = 0.0; g_sumsq = 0.0; }
    int gw   = (blockIdx.x * blockDim.x + threadIdx.x) >> 5;
    int lane = threadIdx.x & 31;
    if (gw >= NROWS) return;
    const float4* row = (const float4*)(x + (size_t)gw * EDIM);
    uint4* op = (uint4*)(g_h + (size_t)gw * EDIM);
    float s = 0.f;
    #pragma unroll
    for (int p = 0; p < 2; p++) {
        int u = lane + 32 * p;
        float4 a = row[2 * u];
        float4 b = row[2 * u + 1];
        s += a.x*a.x + a.y*a.y + a.z*a.z + a.w*a.w;
        s += b.x*b.x + b.y*b.y + b.z*b.z + b.w*b.w;
        __half2 h[4];
        h[0] = __floats2half2_rn(a.x, a.y);
        h[1] = __floats2half2_rn(a.z, a.w);
        h[2] = __floats2half2_rn(b.x, b.y);
        h[3] = __floats2half2_rn(b.z, b.w);
        op[u] = *(uint4*)h;
    }
    #pragma unroll
    for (int o = 16; o > 0; o >>= 1) s += __shfl_xor_sync(0xffffffffu, s, o);
    if (lane == 0) g_sq[gw] = s;
}

// ---------------------------------------------------------------------------
// Kernel 2: symmetric fp16 Gram -> u16 fixed-point d (d*16).
// Round-6 loop SHAPE (prefetch->commit->wait->sync->mma->sync) with KC=64:
// 8 chunks, 16 barriers total. Warp-coalesced u16 epilogue from round 11.
// ---------------------------------------------------------------------------
__device__ __forceinline__ void prefetch_chunk(
    const __half* A, const __half* B, uint32_t sb, int buf, int kc, int tid)
{
    const __half* panels[NTILES] = { A, B };
    int p = tid >> 6, s = tid & 63;          // 64 threads per panel
    const char* src = (const char*)panels[p] + kc * (KC * 2);
    uint32_t tb = sb + SM_TILES + buf * BUF_B + p * TILE_B;
    #pragma unroll
    for (int i = 0; i < 16; i++) {
        int idx = i * 64 + s;                // 0..1023 (16B granules)
        int row = idx >> 3;                  // 0..127
        int q   = idx & 7;                   // 0..7
        cp16(tb + row * TROWB + q * 16,
             src + (size_t)row * (EDIM * 2) + q * 16);
    }
}

__global__ __launch_bounds__(128, 2)
void gram_tc_kernel() {
    extern __shared__ char smem[];
    const uint32_t sb = smem_u32(smem);
    const int tid  = threadIdx.x;
    const int wid  = tid >> 5;
    const int lane = tid & 31;

    // decode upper-triangle tile pair (8x8 tiles, 36 pairs)
    int p = blockIdx.x, ti = 0;
    while (p >= 8 - ti) { p -= 8 - ti; ti++; }
    const int tj   = ti + p;
    const int b    = blockIdx.z;
    const int row0 = ti * 128;
    const int col0 = tj * 128;
    const int warp_m = (wid >> 1) * 64;
    const int warp_n = (wid & 1) * 64;

    const __half* A = g_h + ((size_t)(b * SEQ + row0)) * EDIM;
    const __half* B = g_h + ((size_t)(b * SEQ + col0)) * EDIM;

    if (tid < 128) {
        ((float*)(smem + SM_SQA))[tid] = g_sq[b * SEQ + row0 + tid];
        ((float*)(smem + SM_SQB))[tid] = g_sq[b * SEQ + col0 + tid];
    }

    float acc[4][8][4];
    #pragma unroll
    for (int mi = 0; mi < 4; mi++)
        #pragma unroll
        for (int ni = 0; ni < 8; ni++)
            #pragma unroll
            for (int k = 0; k < 4; k++) acc[mi][ni][k] = 0.f;

    const uint32_t aOff = (uint32_t)((warp_m + (lane & 15)) * TROWB + (lane >> 4) * 16);
    const uint32_t bOff = (uint32_t)((warp_n + (lane & 7) + ((lane >> 4) << 3)) * TROWB
                                     + ((lane >> 3) & 1) * 16);

    prefetch_chunk(A, B, sb, 0, 0, tid);
    CP_COMMIT();

    #pragma unroll 1
    for (int c = 0; c < NCHUNK; c++) {
        if (c + 1 < NCHUNK) {
            prefetch_chunk(A, B, sb, (c + 1) & 1, c + 1, tid);
            CP_COMMIT();
            CP_WAIT(1);
        } else {
            CP_WAIT(0);
        }
        __syncthreads();

        uint32_t base = sb + SM_TILES + (c & 1) * BUF_B;
        #pragma unroll
        for (int ks = 0; ks < 4; ks++) {               // 4 k-steps of 16
            const uint32_t kb = ks * 32;
            uint32_t aF[16], bb[16];
            #pragma unroll
            for (int mi = 0; mi < 4; mi++)
                ldm4(&aF[mi * 4], base + 0 * TILE_B + aOff + mi * 16 * TROWB + kb);
            #pragma unroll
            for (int nj = 0; nj < 4; nj++)
                ldm4(&bb[nj * 4], base + 1 * TILE_B + bOff + nj * 16 * TROWB + kb);
            #pragma unroll
            for (int mi = 0; mi < 4; mi++)
                #pragma unroll
                for (int ni = 0; ni < 8; ni++)
                    mma16816(acc[mi][ni], &aF[mi * 4], bb[ni * 2], bb[ni * 2 + 1]);
        }
        __syncthreads();
    }

    // ---------------- epilogue: stage fp32 d in smem, stats, u16 writes ---
    const int g  = lane >> 2;
    const int t4 = lane & 3;
    const float* sqA = (const float*)(smem + SM_SQA);
    const float* sqB = (const float*)(smem + SM_SQB);
    float* trb = (float*)(smem + SM_TILES);
    unsigned short* Dd = g_d + (size_t)b * SEQ * SEQ;
    const bool diag = (ti == tj);
    float fsum = 0.f, fsq = 0.f;
    #pragma unroll
    for (int mi = 0; mi < 4; mi++) {
        #pragma unroll
        for (int h = 0; h < 2; h++) {
            int rl = warp_m + mi * 16 + g + h * 8;
            float sr = sqA[rl];
            #pragma unroll
            for (int ni = 0; ni < 8; ni++) {
                int cl = warp_n + ni * 8 + t4 * 2;
                float d0 = fmaxf(sr + sqB[cl]     - 2.f * acc[mi][ni][2 * h],     0.f);
                float d1 = fmaxf(sr + sqB[cl + 1] - 2.f * acc[mi][ni][2 * h + 1], 0.f);
                if (diag) {                    // exact-zero self distance
                    if (rl == cl)     d0 = 0.f;
                    if (rl == cl + 1) d1 = 0.f;
                }
                fsum += d0 + d1;
                fsq  += d0 * d0 + d1 * d1;
                trb[rl * TRPAD + cl]     = d0;
                trb[rl * TRPAD + cl + 1] = d1;
            }
        }
    }
    __syncthreads();   // trb fully written

    // direct tile (ti,tj): warp handles 32 rows; per row, 32 lanes x ushort4
    // = 256B fully-coalesced store.
    #pragma unroll 4
    for (int r32 = 0; r32 < 32; r32++) {
        int r = wid * 32 + r32;
        const float* tp = trb + r * TRPAD + lane * 4;
        ushort4 u;
        u.x = q16(tp[0]); u.y = q16(tp[1]);
        u.z = q16(tp[2]); u.w = q16(tp[3]);
        *(ushort4*)(Dd + (size_t)(row0 + r) * SEQ + col0 + lane * 4) = u;
    }

    if (!diag) {       // transposed tile (tj,ti): coalesced row writes,
                       // smem column gather (TRPAD=129 -> conflict-free)
        #pragma unroll 4
        for (int r32 = 0; r32 < 32; r32++) {
            int cc = wid * 32 + r32;
            ushort4 u;
            u.x = q16(trb[(lane * 4 + 0) * TRPAD + cc]);
            u.y = q16(trb[(lane * 4 + 1) * TRPAD + cc]);
            u.z = q16(trb[(lane * 4 + 2) * TRPAD + cc]);
            u.w = q16(trb[(lane * 4 + 3) * TRPAD + cc]);
            *(ushort4*)(Dd + (size_t)(col0 + cc) * SEQ + row0 + lane * 4) = u;
        }
        fsum *= 2.f; fsq *= 2.f;
    }

    // stats reduction (fp32 warp -> double CTA -> 2 atomics)
    #pragma unroll
    for (int o = 16; o > 0; o >>= 1) {
        fsum += __shfl_xor_sync(0xffffffffu, fsum, o);
        fsq  += __shfl_xor_sync(0xffffffffu, fsq,  o);
    }
    if (lane == 0) {
        ((double*)(smem + SM_RED))[wid]  = (double)fsum;
        ((double*)(smem + SM_REDQ))[wid] = (double)fsq;
    }
    __syncthreads();
    if (tid == 0) {
        double s = 0.0, q = 0.0;
        #pragma unroll
        for (int k = 0; k < 4; k++) {
            s += ((double*)(smem + SM_RED))[k];
            q += ((double*)(smem + SM_REDQ))[k];
        }
        atomicAdd(&g_sum, s);
        atomicAdd(&g_sumsq, q);
    }
}

// ---------------------------------------------------------------------------
// Kernel 3: warp-per-row softmax. Reads u16 d, writes fp32 probs to out.
// coef from global stats in FLOAT; dequant scale folded into coef.
// Row max analytically 0 when coef <= 0 (u_ii = 0 in every row).
// ---------------------------------------------------------------------------
__global__ __launch_bounds__(256)
void softmax_kernel(float* __restrict__ dout, const float* __restrict__ gamma) {
    const int wid  = threadIdx.x >> 5;
    const int lane = threadIdx.x & 31;
    const size_t row = (size_t)blockIdx.x * 8 + wid;
    const ushort4* ip = (const ushort4*)(g_d + row * SEQ);
    float4* op = (float4*)(dout + row * SEQ);

    const float fsum0 = (float)g_sum;
    const float fssq  = (float)g_sumsq;
    const float mean  = fsum0 * (1.f / TOTALF);
    const float var   = fssq * (1.f / TOTALF) - mean * mean;
    const float coef  = -gamma[0] * rsqrtf(var + EPSV) * (1.f / TEMP);
    const float c2    = coef * INV_DSCALE;

    float t[32];
    #pragma unroll
    for (int i = 0; i < 8; i++) {
        ushort4 u = ip[lane + 32 * i];
        t[4*i+0] = c2 * (float)u.x;
        t[4*i+1] = c2 * (float)u.y;
        t[4*i+2] = c2 * (float)u.z;
        t[4*i+3] = c2 * (float)u.w;
    }

    float m = 0.f;
    if (coef > 0.f) {            // not taken for gamma>0; correctness guard
        m = -1e30f;
        #pragma unroll
        for (int j = 0; j < 32; j++) m = fmaxf(m, t[j]);
        #pragma unroll
        for (int o = 16; o > 0; o >>= 1) m = fmaxf(m, __shfl_xor_sync(0xffffffffu, m, o));
    }

    float s = 0.f;
    #pragma unroll
    for (int j = 0; j < 32; j++) { t[j] = __expf(t[j] - m); s += t[j]; }
    #pragma unroll
    for (int o = 16; o > 0; o >>= 1) s += __shfl_xor_sync(0xffffffffu, s, o);
    const float inv = 1.f / s;

    #pragma unroll
    for (int i = 0; i < 8; i++) {
        float4 v;
        v.x = t[4*i+0] * inv; v.y = t[4*i+1] * inv;
        v.z = t[4*i+2] * inv; v.w = t[4*i+3] * inv;
        op[lane + 32 * i] = v;
    }
}

// ---------------------------------------------------------------------------
extern "C" void kernel_launch(void* const* d_in, const int* in_sizes, int n_in,
                              void* d_out, int out_size) {
    const float* x     = (const float*)d_in[0];
    const float* gamma = (const float*)d_in[1];
    float* out = (float*)d_out;

    cudaFuncSetAttribute(gram_tc_kernel,
                         cudaFuncAttributeMaxDynamicSharedMemorySize, GRAM_SMEM);

    conv_kernel<<<NROWS * 32 / 256, 256>>>(x);
    dim3 grid(36, 1, BATCH);
    gram_tc_kernel<<<grid, 128, GRAM_SMEM>>>();
    softmax_kernel<<<NROWS / 8, 256>>>(out, gamma);
}